// round 3
// baseline (speedup 1.0000x reference)
#include <cuda_runtime.h>
#include <cstdint>
#include <math.h>

#define B 32
#define T 256
#define DI 512
#define H 1024
#define G4 (4*H)
#define G5 (5*H)
#define TBH ((size_t)T*(size_t)B*(size_t)H)
#define NBLK 128

// Scratch (allocation-free: __device__ globals)
__device__ float g_pre[(size_t)T*B*G5];     // gate pre-activations (ld 4096 or 5120)
__device__ float g_hbuf[2*TBH];             // ping-pong h sequences, layout (t,b,j)
__device__ float g_cbuf[2*TBH];             // ping-pong c sequences

// Grid barrier state
__device__ unsigned g_cnt;
__device__ volatile unsigned g_gen;

__device__ __forceinline__ float sigf(float x) { return 1.0f / (1.0f + __expf(-x)); }

// All-blocks barrier. Every thread fences (global visibility of this block's
// stores), then one thread per block arrives; last block bumps the generation.
__device__ __forceinline__ void grid_bar()
{
    __threadfence();
    __syncthreads();
    if (threadIdx.x == 0) {
        unsigned my = g_gen;
        if (atomicAdd(&g_cnt, 1u) == NBLK - 1) {
            atomicExch(&g_cnt, 0u);
            __threadfence();
            g_gen = my + 1;
        } else {
            while (g_gen == my) { __nanosleep(100); }
        }
    }
    __syncthreads();
}

// ---------------------------------------------------------------------------
// Generic GEMM: C[row(m)][n] = sum_k A[m][k] * W[n][k] + b0[n] (+ b1[n])
// Tile 128x128, BK=8, 256 threads, 8x8 register blocking.
// swapMT: m = b*T + t  ->  output row = t*B + b  (layer-0 input projection)
// ---------------------------------------------------------------------------
__global__ __launch_bounds__(256) void gemm_bias(
    const float* __restrict__ A, int lda,
    const float* __restrict__ W, int ldw,
    const float* __restrict__ b0, const float* __restrict__ b1,
    float* __restrict__ C, int ldc, int K, int swapMT)
{
    __shared__ float As[8][128];
    __shared__ float Bs[8][128];

    const int tid = threadIdx.x;
    const int m0 = blockIdx.y * 128;
    const int n0 = blockIdx.x * 128;
    const int tx = tid & 15;
    const int ty = tid >> 4;

    const int ar = tid >> 1;
    const int ac = (tid & 1) * 4;
    const float* Ap = A + (size_t)(m0 + ar) * lda + ac;
    const float* Wp = W + (size_t)(n0 + ar) * ldw + ac;

    float acc[8][8];
#pragma unroll
    for (int i = 0; i < 8; i++)
#pragma unroll
        for (int j = 0; j < 8; j++) acc[i][j] = 0.0f;

    for (int k0 = 0; k0 < K; k0 += 8) {
        float4 av = *reinterpret_cast<const float4*>(Ap + k0);
        float4 wv = *reinterpret_cast<const float4*>(Wp + k0);
        __syncthreads();
        As[ac + 0][ar] = av.x; As[ac + 1][ar] = av.y;
        As[ac + 2][ar] = av.z; As[ac + 3][ar] = av.w;
        Bs[ac + 0][ar] = wv.x; Bs[ac + 1][ar] = wv.y;
        Bs[ac + 2][ar] = wv.z; Bs[ac + 3][ar] = wv.w;
        __syncthreads();
#pragma unroll
        for (int kk = 0; kk < 8; kk++) {
            float a[8], bb[8];
#pragma unroll
            for (int i = 0; i < 8; i++) a[i] = As[kk][ty * 8 + i];
#pragma unroll
            for (int j = 0; j < 8; j++) bb[j] = Bs[kk][tx * 8 + j];
#pragma unroll
            for (int i = 0; i < 8; i++)
#pragma unroll
                for (int j = 0; j < 8; j++) acc[i][j] += a[i] * bb[j];
        }
    }

#pragma unroll
    for (int j = 0; j < 8; j++) {
        int n = n0 + tx * 8 + j;
        float bias = b0[n] + (b1 ? b1[n] : 0.0f);
#pragma unroll
        for (int i = 0; i < 8; i++) {
            int m = m0 + ty * 8 + i;
            int row = swapMT ? ((m & (T - 1)) * B + (m >> 8)) : m;
            C[(size_t)row * ldc + n] = acc[i][j] + bias;
        }
    }
}

// ---------------------------------------------------------------------------
// Persistent layer-0 LSTM scan. 128 blocks x 256 threads, all co-resident.
// Block owns 8 j-units x 4 gates. W (32 rows x 1024 k = 128KB) resident in
// dynamic smem for the whole kernel; h_prev staged transposed per 128-k chunk.
// One grid barrier per timestep.
// ---------------------------------------------------------------------------
__global__ __launch_bounds__(256) void lstm0_scan(const float* __restrict__ Whh)
{
    extern __shared__ float smemf[];
    float4* ws4 = reinterpret_cast<float4*>(smemf);   // [32][256] float4
    float*  hT  = smemf + 32 * 256 * 4;               // [128][32]

    const int tid = threadIdx.x;
    const int jbase = blockIdx.x * 8;
    const int b = tid & 31;
    const int jj = tid >> 5;

    // Load W once: rows (g*8+r) -> Whh row g*H + jbase + r, all 1024 k.
    for (int i = tid; i < 32 * 256; i += 256) {
        int r = i >> 8, kq = i & 255;
        int grow = ((r >> 3) << 10) + jbase + (r & 7);
        ws4[i] = *reinterpret_cast<const float4*>(Whh + (size_t)grow * H + kq * 4);
    }
    __syncthreads();

    for (int t = 0; t < T; t++) {
        float a0 = 0.f, a1 = 0.f, a2 = 0.f, a3 = 0.f;

        if (t > 0) {
            const float* hprev = g_hbuf + (size_t)(t - 1) * (B * H);
            for (int kc = 0; kc < H; kc += 128) {
                for (int i = tid; i < 1024; i += 256) {
                    int bb = i & 31, kq = i >> 5;
                    float4 hv = *reinterpret_cast<const float4*>(hprev + (size_t)bb * H + kc + kq * 4);
                    hT[(kq * 4 + 0) * 32 + bb] = hv.x; hT[(kq * 4 + 1) * 32 + bb] = hv.y;
                    hT[(kq * 4 + 2) * 32 + bb] = hv.z; hT[(kq * 4 + 3) * 32 + bb] = hv.w;
                }
                __syncthreads();
                const int kq0 = kc >> 2;
#pragma unroll 8
                for (int kk = 0; kk < 128; kk += 4) {
                    float h0 = hT[(kk + 0) * 32 + b], h1 = hT[(kk + 1) * 32 + b];
                    float h2 = hT[(kk + 2) * 32 + b], h3 = hT[(kk + 3) * 32 + b];
                    int kq = kq0 + (kk >> 2);
                    float4 w;
                    w = ws4[(0 * 8 + jj) * 256 + kq]; a0 += w.x * h0 + w.y * h1 + w.z * h2 + w.w * h3;
                    w = ws4[(1 * 8 + jj) * 256 + kq]; a1 += w.x * h0 + w.y * h1 + w.z * h2 + w.w * h3;
                    w = ws4[(2 * 8 + jj) * 256 + kq]; a2 += w.x * h0 + w.y * h1 + w.z * h2 + w.w * h3;
                    w = ws4[(3 * 8 + jj) * 256 + kq]; a3 += w.x * h0 + w.y * h1 + w.z * h2 + w.w * h3;
                }
                __syncthreads();
            }
        }

        const int j = jbase + jj;
        const float* xp = g_pre + ((size_t)t * B + b) * G4;
        float gi = a0 + xp[0 * H + j];
        float gf = a1 + xp[1 * H + j];
        float gg = a2 + xp[2 * H + j];
        float go = a3 + xp[3 * H + j];
        float cp = (t > 0) ? g_cbuf[((size_t)(t - 1) * B + b) * H + j] : 0.0f;
        float c = sigf(gf) * cp + sigf(gi) * tanhf(gg);
        float h = sigf(go) * tanhf(c);
        size_t o = ((size_t)t * B + b) * H + j;
        g_hbuf[o] = h;
        g_cbuf[o] = c;

        grid_bar();
    }
}

// ---------------------------------------------------------------------------
// Persistent CA-LSTM scan (layers 1..3). 5 gates, W_prev (rows stride 2H)
// resident in smem (160KB). Reads c_low from src buffers, writes dst.
// ---------------------------------------------------------------------------
__global__ __launch_bounds__(256) void ca_scan(const float* __restrict__ Wp, int src, int dst)
{
    extern __shared__ float smemf[];
    float4* ws4 = reinterpret_cast<float4*>(smemf);   // [40][256] float4
    float*  hT  = smemf + 40 * 256 * 4;               // [128][32]

    const int tid = threadIdx.x;
    const int jbase = blockIdx.x * 8;
    const int b = tid & 31;
    const int jj = tid >> 5;

    for (int i = tid; i < 40 * 256; i += 256) {
        int r = i >> 8, kq = i & 255;
        int grow = (r >> 3) * H + jbase + (r & 7);
        ws4[i] = *reinterpret_cast<const float4*>(Wp + (size_t)grow * (2 * H) + kq * 4);
    }
    __syncthreads();

    for (int t = 0; t < T; t++) {
        float a0 = 0.f, a1 = 0.f, a2 = 0.f, a3 = 0.f, a4 = 0.f;

        if (t > 0) {
            const float* hprev = g_hbuf + (size_t)dst * TBH + (size_t)(t - 1) * (B * H);
            for (int kc = 0; kc < H; kc += 128) {
                for (int i = tid; i < 1024; i += 256) {
                    int bb = i & 31, kq = i >> 5;
                    float4 hv = *reinterpret_cast<const float4*>(hprev + (size_t)bb * H + kc + kq * 4);
                    hT[(kq * 4 + 0) * 32 + bb] = hv.x; hT[(kq * 4 + 1) * 32 + bb] = hv.y;
                    hT[(kq * 4 + 2) * 32 + bb] = hv.z; hT[(kq * 4 + 3) * 32 + bb] = hv.w;
                }
                __syncthreads();
                const int kq0 = kc >> 2;
#pragma unroll 8
                for (int kk = 0; kk < 128; kk += 4) {
                    float h0 = hT[(kk + 0) * 32 + b], h1 = hT[(kk + 1) * 32 + b];
                    float h2 = hT[(kk + 2) * 32 + b], h3 = hT[(kk + 3) * 32 + b];
                    int kq = kq0 + (kk >> 2);
                    float4 w;
                    w = ws4[(0 * 8 + jj) * 256 + kq]; a0 += w.x * h0 + w.y * h1 + w.z * h2 + w.w * h3;
                    w = ws4[(1 * 8 + jj) * 256 + kq]; a1 += w.x * h0 + w.y * h1 + w.z * h2 + w.w * h3;
                    w = ws4[(2 * 8 + jj) * 256 + kq]; a2 += w.x * h0 + w.y * h1 + w.z * h2 + w.w * h3;
                    w = ws4[(3 * 8 + jj) * 256 + kq]; a3 += w.x * h0 + w.y * h1 + w.z * h2 + w.w * h3;
                    w = ws4[(4 * 8 + jj) * 256 + kq]; a4 += w.x * h0 + w.y * h1 + w.z * h2 + w.w * h3;
                }
                __syncthreads();
            }
        }

        const int j = jbase + jj;
        const float* pre = g_pre + ((size_t)t * B + b) * G5;
        float gi  = a0 + pre[0 * H + j];
        float gfp = a1 + pre[1 * H + j];
        float gfl = a2 + pre[2 * H + j];
        float gu  = a3 + pre[3 * H + j];
        float go  = a4 + pre[4 * H + j];

        size_t idx = ((size_t)t * B + b) * H + j;
        float cp = (t > 0) ? g_cbuf[(size_t)dst * TBH + idx - (size_t)(B * H)] : 0.0f;
        float cl = g_cbuf[(size_t)src * TBH + idx];
        float c = cp * sigf(gfp + 1.0f) + cl * sigf(gfl + 1.0f) + tanhf(gu) * sigf(gi);
        float h = sigf(go) * tanhf(c);
        g_hbuf[(size_t)dst * TBH + idx] = h;
        g_cbuf[(size_t)dst * TBH + idx] = c;

        grid_bar();
    }
}

// ---------------------------------------------------------------------------
// Final transpose (t,b,j) -> (b,t,j); h then c into d_out.
// ---------------------------------------------------------------------------
__global__ __launch_bounds__(256) void finalize(int fin, float* __restrict__ out)
{
    size_t gid = (size_t)blockIdx.x * 256 + threadIdx.x;
    int j = (int)(gid & (H - 1));
    int bt = (int)(gid >> 10);
    int t = bt & (T - 1);
    int b = bt >> 8;
    size_t srci = ((size_t)t * B + b) * H + j;
    out[gid]       = g_hbuf[(size_t)fin * TBH + srci];
    out[TBH + gid] = g_cbuf[(size_t)fin * TBH + srci];
}

// ---------------------------------------------------------------------------
extern "C" void kernel_launch(void* const* d_in, const int* in_sizes, int n_in,
                              void* d_out, int out_size)
{
    (void)in_sizes; (void)n_in; (void)out_size;
    const float* inputs = (const float*)d_in[0];
    const float* W_ih0  = (const float*)d_in[1];
    const float* W_hh0  = (const float*)d_in[2];
    const float* b_ih0  = (const float*)d_in[3];
    const float* b_hh0  = (const float*)d_in[4];
    const float* W_ca   = (const float*)d_in[5];
    const float* b_ca   = (const float*)d_in[6];
    float* out = (float*)d_out;

    float* pre = nullptr;
    float* hb  = nullptr;
    cudaGetSymbolAddress((void**)&pre, g_pre);
    cudaGetSymbolAddress((void**)&hb,  g_hbuf);

    const int smem0 = 32 * 256 * 16 + 128 * 32 * 4;   // 147456
    const int smemC = 40 * 256 * 16 + 128 * 32 * 4;   // 180224
    cudaFuncSetAttribute(lstm0_scan, cudaFuncAttributeMaxDynamicSharedMemorySize, smem0);
    cudaFuncSetAttribute(ca_scan,    cudaFuncAttributeMaxDynamicSharedMemorySize, smemC);

    // Layer 0: xp[t][b][g] = x @ W_ih0^T + (b_ih0 + b_hh0)
    gemm_bias<<<dim3(G4 / 128, (B * T) / 128), 256>>>(
        inputs, DI, W_ih0, DI, b_ih0, b_hh0, pre, G4, DI, 1);
    lstm0_scan<<<NBLK, 256, smem0>>>(W_hh0);

    int src = 0;
    for (int l = 0; l < 3; l++) {
        int dst = 1 - src;
        gemm_bias<<<dim3(G5 / 128, (B * T) / 128), 256>>>(
            hb + (size_t)src * TBH, H,
            W_ca + (size_t)l * G5 * (2 * H), 2 * H,
            b_ca + (size_t)l * G5, nullptr,
            pre, G5, H, 0);
        ca_scan<<<NBLK, 256, smemC>>>(W_ca + (size_t)l * G5 * (2 * H) + H, src, dst);
        src = dst;
    }

    finalize<<<(int)(TBH / 256), 256>>>(src, out);
}

// round 4
// speedup vs baseline: 1.4810x; 1.4810x over previous
#include <cuda_runtime.h>
#include <cstdint>
#include <math.h>

#define B 32
#define T 256
#define DI 512
#define H 1024
#define G4 (4*H)
#define G5 (5*H)
#define TBH ((size_t)T*(size_t)B*(size_t)H)
#define NBLK 128

typedef unsigned long long ull;

// Scratch (allocation-free: __device__ globals)
__device__ float g_pre[(size_t)T*B*G5];     // gate pre-activations
__device__ float g_hbuf[2*TBH];             // ping-pong h sequences, layout (t,b,j)
__device__ float g_cbuf[2*TBH];             // ping-pong c sequences

// Grid barrier state
__device__ unsigned g_cnt;
__device__ volatile unsigned g_gen;

__device__ __forceinline__ float sigf(float x) { return 1.0f / (1.0f + __expf(-x)); }

// Packed f32x2 FMA: d.lo += a.lo*b.lo, d.hi += a.hi*b.hi (1 issue, 2 MACs)
__device__ __forceinline__ void fma2(ull& d, ull a, ull b) {
    asm("fma.rn.f32x2 %0, %1, %2, %0;" : "+l"(d) : "l"(a), "l"(b));
}
__device__ __forceinline__ ull packdup(float x) {
    ull r; asm("mov.b64 %0, {%1, %1};" : "=l"(r) : "f"(x)); return r;
}
__device__ __forceinline__ float2 unpack2(ull v) {
    float2 f; asm("mov.b64 {%0, %1}, %2;" : "=f"(f.x), "=f"(f.y) : "l"(v)); return f;
}

// All-blocks barrier. bar.sync cumulativity orders every thread's prior
// stores before tid0's fence+arrive; waiters fence after release observed.
__device__ __forceinline__ void grid_bar()
{
    __syncthreads();
    if (threadIdx.x == 0) {
        __threadfence();
        unsigned my = g_gen;
        if (atomicAdd(&g_cnt, 1u) == NBLK - 1) {
            atomicExch(&g_cnt, 0u);
            __threadfence();
            g_gen = my + 1;
        } else {
            while (g_gen == my) { __nanosleep(64); }
            __threadfence();
        }
    }
    __syncthreads();
}

// ---------------------------------------------------------------------------
// GEMM: C[row(m)][n] = sum_k A[m][k] * W[n][k] + b0[n] (+ b1[n])
// 128x128 tile, BK=8, 256 threads, 8x8 per thread, f32x2 packed FMA.
// ---------------------------------------------------------------------------
__global__ __launch_bounds__(256) void gemm_bias(
    const float* __restrict__ A, int lda,
    const float* __restrict__ W, int ldw,
    const float* __restrict__ b0, const float* __restrict__ b1,
    float* __restrict__ C, int ldc, int K, int swapMT)
{
    __shared__ float As[8][128];
    __shared__ float Bs[8][128];

    const int tid = threadIdx.x;
    const int m0 = blockIdx.y * 128;
    const int n0 = blockIdx.x * 128;
    const int tx = tid & 15;
    const int ty = tid >> 4;

    const int ar = tid >> 1;
    const int ac = (tid & 1) * 4;
    const float* Ap = A + (size_t)(m0 + ar) * lda + ac;
    const float* Wp = W + (size_t)(n0 + ar) * ldw + ac;

    ull acc2[8][4];
#pragma unroll
    for (int i = 0; i < 8; i++)
#pragma unroll
        for (int jp = 0; jp < 4; jp++) acc2[i][jp] = 0ULL;

    for (int k0 = 0; k0 < K; k0 += 8) {
        float4 av = *reinterpret_cast<const float4*>(Ap + k0);
        float4 wv = *reinterpret_cast<const float4*>(Wp + k0);
        __syncthreads();
        As[ac + 0][ar] = av.x; As[ac + 1][ar] = av.y;
        As[ac + 2][ar] = av.z; As[ac + 3][ar] = av.w;
        Bs[ac + 0][ar] = wv.x; Bs[ac + 1][ar] = wv.y;
        Bs[ac + 2][ar] = wv.z; Bs[ac + 3][ar] = wv.w;
        __syncthreads();
#pragma unroll
        for (int kk = 0; kk < 8; kk++) {
            const float4* arow = reinterpret_cast<const float4*>(&As[kk][ty * 8]);
            float4 alo = arow[0], ahi = arow[1];
            const ulonglong2* brow = reinterpret_cast<const ulonglong2*>(&Bs[kk][tx * 8]);
            ulonglong2 b01 = brow[0], b23 = brow[1];
            float a[8] = {alo.x, alo.y, alo.z, alo.w, ahi.x, ahi.y, ahi.z, ahi.w};
#pragma unroll
            for (int i = 0; i < 8; i++) {
                ull ad = packdup(a[i]);
                fma2(acc2[i][0], ad, b01.x);
                fma2(acc2[i][1], ad, b01.y);
                fma2(acc2[i][2], ad, b23.x);
                fma2(acc2[i][3], ad, b23.y);
            }
        }
    }

    const int nb = n0 + tx * 8;
#pragma unroll
    for (int i = 0; i < 8; i++) {
        int m = m0 + ty * 8 + i;
        int row = swapMT ? ((m & (T - 1)) * B + (m >> 8)) : m;
        float* cr = C + (size_t)row * ldc + nb;
#pragma unroll
        for (int jp = 0; jp < 4; jp++) {
            float2 v = unpack2(acc2[i][jp]);
            int n = nb + jp * 2;
            float bi0 = b0[n]     + (b1 ? b1[n]     : 0.0f);
            float bi1 = b0[n + 1] + (b1 ? b1[n + 1] : 0.0f);
            float2 o; o.x = v.x + bi0; o.y = v.y + bi1;
            *reinterpret_cast<float2*>(cr + jp * 2) = o;
        }
    }
}

// ---------------------------------------------------------------------------
// Persistent layer-0 LSTM scan. 128 blocks x 256 threads. W resident in smem
// (128KB); h staged per 512-k chunk as float4-of-k, pad-33 (64KB+pad).
// ---------------------------------------------------------------------------
__global__ __launch_bounds__(256) void lstm0_scan(const float* __restrict__ Whh)
{
    extern __shared__ float smemf[];
    float4* ws4 = reinterpret_cast<float4*>(smemf);              // [32][256]
    float4* hT4 = reinterpret_cast<float4*>(smemf + 32*256*4);   // [128][33]

    const int tid = threadIdx.x;
    const int jbase = blockIdx.x * 8;
    const int b = tid & 31;
    const int jj = tid >> 5;
    const int j = jbase + jj;

    for (int i = tid; i < 32 * 256; i += 256) {
        int r = i >> 8, kq = i & 255;
        int grow = ((r >> 3) << 10) + jbase + (r & 7);
        ws4[i] = *reinterpret_cast<const float4*>(Whh + (size_t)grow * H + kq * 4);
    }
    __syncthreads();

    for (int t = 0; t < T; t++) {
        // Prefetch gate pre-activations + c_prev (overlaps with k-loop)
        const float* xp = g_pre + ((size_t)t * B + b) * G4 + j;
        float pg0 = xp[0*H], pg1 = xp[1*H], pg2 = xp[2*H], pg3 = xp[3*H];
        float cp = 0.0f;
        if (t > 0) cp = g_cbuf[((size_t)(t - 1) * B + b) * H + j];

        ull acc[4][2];
#pragma unroll
        for (int g = 0; g < 4; g++) { acc[g][0] = 0ULL; acc[g][1] = 0ULL; }

        if (t > 0) {
            const float* hprev = g_hbuf + (size_t)(t - 1) * (B * H);
#pragma unroll 1
            for (int c = 0; c < 2; c++) {
                const int kc = c * 512;
#pragma unroll
                for (int i = tid; i < 4096; i += 256) {
                    int bb = i >> 7, kql = i & 127;
                    hT4[kql * 33 + bb] =
                        *reinterpret_cast<const float4*>(hprev + (size_t)bb * H + kc + kql * 4);
                }
                __syncthreads();
                const int kq0 = kc >> 2;
#pragma unroll 8
                for (int kq = 0; kq < 128; kq++) {
                    ulonglong2 hv = *reinterpret_cast<const ulonglong2*>(&hT4[kq * 33 + b]);
                    int kqg = kq0 + kq;
#pragma unroll
                    for (int g = 0; g < 4; g++) {
                        ulonglong2 wv = *reinterpret_cast<const ulonglong2*>(
                            &ws4[(g * 8 + jj) * 256 + kqg]);
                        fma2(acc[g][0], wv.x, hv.x);
                        fma2(acc[g][1], wv.y, hv.y);
                    }
                }
                __syncthreads();
            }
        }

        float2 s0a = unpack2(acc[0][0]), s0b = unpack2(acc[0][1]);
        float2 s1a = unpack2(acc[1][0]), s1b = unpack2(acc[1][1]);
        float2 s2a = unpack2(acc[2][0]), s2b = unpack2(acc[2][1]);
        float2 s3a = unpack2(acc[3][0]), s3b = unpack2(acc[3][1]);
        float gi = pg0 + s0a.x + s0a.y + s0b.x + s0b.y;
        float gf = pg1 + s1a.x + s1a.y + s1b.x + s1b.y;
        float gg = pg2 + s2a.x + s2a.y + s2b.x + s2b.y;
        float go = pg3 + s3a.x + s3a.y + s3b.x + s3b.y;

        float cc = sigf(gf) * cp + sigf(gi) * tanhf(gg);
        float h  = sigf(go) * tanhf(cc);
        size_t o = ((size_t)t * B + b) * H + j;
        g_hbuf[o] = h;
        g_cbuf[o] = cc;

        if (t < T - 1) grid_bar();
    }
}

// ---------------------------------------------------------------------------
// Persistent CA-LSTM scan (layers 1..3). 5 gates, W_prev resident (160KB).
// ---------------------------------------------------------------------------
__global__ __launch_bounds__(256) void ca_scan(const float* __restrict__ Wp, int src, int dst)
{
    extern __shared__ float smemf[];
    float4* ws4 = reinterpret_cast<float4*>(smemf);              // [40][256]
    float4* hT4 = reinterpret_cast<float4*>(smemf + 40*256*4);   // [128][33]

    const int tid = threadIdx.x;
    const int jbase = blockIdx.x * 8;
    const int b = tid & 31;
    const int jj = tid >> 5;
    const int j = jbase + jj;

    for (int i = tid; i < 40 * 256; i += 256) {
        int r = i >> 8, kq = i & 255;
        int grow = (r >> 3) * H + jbase + (r & 7);
        ws4[i] = *reinterpret_cast<const float4*>(Wp + (size_t)grow * (2 * H) + kq * 4);
    }
    __syncthreads();

    for (int t = 0; t < T; t++) {
        const float* pre = g_pre + ((size_t)t * B + b) * G5 + j;
        float pg0 = pre[0*H], pg1 = pre[1*H], pg2 = pre[2*H], pg3 = pre[3*H], pg4 = pre[4*H];
        size_t idx = ((size_t)t * B + b) * H + j;
        float cl = g_cbuf[(size_t)src * TBH + idx];
        float cp = 0.0f;
        if (t > 0) cp = g_cbuf[(size_t)dst * TBH + idx - (size_t)(B * H)];

        ull acc[5][2];
#pragma unroll
        for (int g = 0; g < 5; g++) { acc[g][0] = 0ULL; acc[g][1] = 0ULL; }

        if (t > 0) {
            const float* hprev = g_hbuf + (size_t)dst * TBH + (size_t)(t - 1) * (B * H);
#pragma unroll 1
            for (int c = 0; c < 2; c++) {
                const int kc = c * 512;
#pragma unroll
                for (int i = tid; i < 4096; i += 256) {
                    int bb = i >> 7, kql = i & 127;
                    hT4[kql * 33 + bb] =
                        *reinterpret_cast<const float4*>(hprev + (size_t)bb * H + kc + kql * 4);
                }
                __syncthreads();
                const int kq0 = kc >> 2;
#pragma unroll 8
                for (int kq = 0; kq < 128; kq++) {
                    ulonglong2 hv = *reinterpret_cast<const ulonglong2*>(&hT4[kq * 33 + b]);
                    int kqg = kq0 + kq;
#pragma unroll
                    for (int g = 0; g < 5; g++) {
                        ulonglong2 wv = *reinterpret_cast<const ulonglong2*>(
                            &ws4[(g * 8 + jj) * 256 + kqg]);
                        fma2(acc[g][0], wv.x, hv.x);
                        fma2(acc[g][1], wv.y, hv.y);
                    }
                }
                __syncthreads();
            }
        }

        float sg[5];
#pragma unroll
        for (int g = 0; g < 5; g++) {
            float2 a = unpack2(acc[g][0]), bv = unpack2(acc[g][1]);
            sg[g] = a.x + a.y + bv.x + bv.y;
        }
        float gi  = sg[0] + pg0;
        float gfp = sg[1] + pg1;
        float gfl = sg[2] + pg2;
        float gu  = sg[3] + pg3;
        float go  = sg[4] + pg4;

        float cc = cp * sigf(gfp + 1.0f) + cl * sigf(gfl + 1.0f) + tanhf(gu) * sigf(gi);
        float h  = sigf(go) * tanhf(cc);
        g_hbuf[(size_t)dst * TBH + idx] = h;
        g_cbuf[(size_t)dst * TBH + idx] = cc;

        if (t < T - 1) grid_bar();
    }
}

// ---------------------------------------------------------------------------
// Final transpose (t,b,j) -> (b,t,j); h then c into d_out.
// ---------------------------------------------------------------------------
__global__ __launch_bounds__(256) void finalize(int fin, float* __restrict__ out)
{
    size_t gid = (size_t)blockIdx.x * 256 + threadIdx.x;
    int j = (int)(gid & (H - 1));
    int bt = (int)(gid >> 10);
    int t = bt & (T - 1);
    int b = bt >> 8;
    size_t srci = ((size_t)t * B + b) * H + j;
    out[gid]       = g_hbuf[(size_t)fin * TBH + srci];
    out[TBH + gid] = g_cbuf[(size_t)fin * TBH + srci];
}

// ---------------------------------------------------------------------------
extern "C" void kernel_launch(void* const* d_in, const int* in_sizes, int n_in,
                              void* d_out, int out_size)
{
    (void)in_sizes; (void)n_in; (void)out_size;
    const float* inputs = (const float*)d_in[0];
    const float* W_ih0  = (const float*)d_in[1];
    const float* W_hh0  = (const float*)d_in[2];
    const float* b_ih0  = (const float*)d_in[3];
    const float* b_hh0  = (const float*)d_in[4];
    const float* W_ca   = (const float*)d_in[5];
    const float* b_ca   = (const float*)d_in[6];
    float* out = (float*)d_out;

    float* pre = nullptr;
    float* hb  = nullptr;
    cudaGetSymbolAddress((void**)&pre, g_pre);
    cudaGetSymbolAddress((void**)&hb,  g_hbuf);

    const int smem0 = 32 * 256 * 16 + 128 * 33 * 16;   // 198656
    const int smemC = 40 * 256 * 16 + 128 * 33 * 16;   // 231424
    cudaFuncSetAttribute(lstm0_scan, cudaFuncAttributeMaxDynamicSharedMemorySize, smem0);
    cudaFuncSetAttribute(ca_scan,    cudaFuncAttributeMaxDynamicSharedMemorySize, smemC);

    gemm_bias<<<dim3(G4 / 128, (B * T) / 128), 256>>>(
        inputs, DI, W_ih0, DI, b_ih0, b_hh0, pre, G4, DI, 1);
    lstm0_scan<<<NBLK, 256, smem0>>>(W_hh0);

    int src = 0;
    for (int l = 0; l < 3; l++) {
        int dst = 1 - src;
        gemm_bias<<<dim3(G5 / 128, (B * T) / 128), 256>>>(
            hb + (size_t)src * TBH, H,
            W_ca + (size_t)l * G5 * (2 * H), 2 * H,
            b_ca + (size_t)l * G5, nullptr,
            pre, G5, H, 0);
        ca_scan<<<NBLK, 256, smemC>>>(W_ca + (size_t)l * G5 * (2 * H) + H, src, dst);
        src = dst;
    }

    finalize<<<(int)(TBH / 256), 256>>>(src, out);
}

// round 5
// speedup vs baseline: 1.8278x; 1.2342x over previous
#include <cuda_runtime.h>
#include <cstdint>
#include <math.h>

#define B 32
#define T 256
#define DI 512
#define H 1024
#define G4 (4*H)
#define G5 (5*H)
#define TBH ((size_t)T*(size_t)B*(size_t)H)
#define NBLK 128

typedef unsigned long long ull;

// Scratch (allocation-free: __device__ globals)
__device__ float g_pre[(size_t)T*B*G5];     // gate pre-activations
__device__ float g_hbuf[2*TBH];             // ping-pong h sequences, layout (t,b,j)
__device__ float g_cbuf[2*TBH];             // ping-pong c sequences

// Grid barrier state
__device__ unsigned g_cnt;
__device__ volatile unsigned g_gen;

__device__ __forceinline__ float sigf(float x) { return 1.0f / (1.0f + __expf(-x)); }

// Packed f32x2 FMA: d.lo += a.lo*b.lo, d.hi += a.hi*b.hi (1 issue, 2 MACs)
__device__ __forceinline__ void fma2(ull& d, ull a, ull b) {
    asm("fma.rn.f32x2 %0, %1, %2, %0;" : "+l"(d) : "l"(a), "l"(b));
}
__device__ __forceinline__ ull packdup(float x) {
    ull r; asm("mov.b64 %0, {%1, %1};" : "=l"(r) : "f"(x)); return r;
}
__device__ __forceinline__ float2 unpack2(ull v) {
    float2 f; asm("mov.b64 {%0, %1}, %2;" : "=f"(f.x), "=f"(f.y) : "l"(v)); return f;
}

// All-blocks barrier.
__device__ __forceinline__ void grid_bar()
{
    __syncthreads();
    if (threadIdx.x == 0) {
        __threadfence();
        unsigned my = g_gen;
        if (atomicAdd(&g_cnt, 1u) == NBLK - 1) {
            atomicExch(&g_cnt, 0u);
            __threadfence();
            g_gen = my + 1;
        } else {
            while (g_gen == my) { __nanosleep(64); }
            __threadfence();
        }
    }
    __syncthreads();
}

// ---------------------------------------------------------------------------
// GEMM: C[row(m)][n] = sum_k A[m][k] * W[n][k] + b0[n] (+ b1[n])
// 128x128 tile, BK=8, 256 threads, 8x8 per thread, f32x2 packed FMA.
// ---------------------------------------------------------------------------
__global__ __launch_bounds__(256) void gemm_bias(
    const float* __restrict__ A, int lda,
    const float* __restrict__ W, int ldw,
    const float* __restrict__ b0, const float* __restrict__ b1,
    float* __restrict__ C, int ldc, int K, int swapMT)
{
    __shared__ float As[8][128];
    __shared__ float Bs[8][128];

    const int tid = threadIdx.x;
    const int m0 = blockIdx.y * 128;
    const int n0 = blockIdx.x * 128;
    const int tx = tid & 15;
    const int ty = tid >> 4;

    const int ar = tid >> 1;
    const int ac = (tid & 1) * 4;
    const float* Ap = A + (size_t)(m0 + ar) * lda + ac;
    const float* Wp = W + (size_t)(n0 + ar) * ldw + ac;

    ull acc2[8][4];
#pragma unroll
    for (int i = 0; i < 8; i++)
#pragma unroll
        for (int jp = 0; jp < 4; jp++) acc2[i][jp] = 0ULL;

    for (int k0 = 0; k0 < K; k0 += 8) {
        float4 av = *reinterpret_cast<const float4*>(Ap + k0);
        float4 wv = *reinterpret_cast<const float4*>(Wp + k0);
        __syncthreads();
        As[ac + 0][ar] = av.x; As[ac + 1][ar] = av.y;
        As[ac + 2][ar] = av.z; As[ac + 3][ar] = av.w;
        Bs[ac + 0][ar] = wv.x; Bs[ac + 1][ar] = wv.y;
        Bs[ac + 2][ar] = wv.z; Bs[ac + 3][ar] = wv.w;
        __syncthreads();
#pragma unroll
        for (int kk = 0; kk < 8; kk++) {
            const float4* arow = reinterpret_cast<const float4*>(&As[kk][ty * 8]);
            float4 alo = arow[0], ahi = arow[1];
            const ulonglong2* brow = reinterpret_cast<const ulonglong2*>(&Bs[kk][tx * 8]);
            ulonglong2 b01 = brow[0], b23 = brow[1];
            float a[8] = {alo.x, alo.y, alo.z, alo.w, ahi.x, ahi.y, ahi.z, ahi.w};
#pragma unroll
            for (int i = 0; i < 8; i++) {
                ull ad = packdup(a[i]);
                fma2(acc2[i][0], ad, b01.x);
                fma2(acc2[i][1], ad, b01.y);
                fma2(acc2[i][2], ad, b23.x);
                fma2(acc2[i][3], ad, b23.y);
            }
        }
    }

    const int nb = n0 + tx * 8;
#pragma unroll
    for (int i = 0; i < 8; i++) {
        int m = m0 + ty * 8 + i;
        int row = swapMT ? ((m & (T - 1)) * B + (m >> 8)) : m;
        float* cr = C + (size_t)row * ldc + nb;
#pragma unroll
        for (int jp = 0; jp < 4; jp++) {
            float2 v = unpack2(acc2[i][jp]);
            int n = nb + jp * 2;
            float bi0 = b0[n]     + (b1 ? b1[n]     : 0.0f);
            float bi1 = b0[n + 1] + (b1 ? b1[n + 1] : 0.0f);
            float2 o; o.x = v.x + bi0; o.y = v.y + bi1;
            *reinterpret_cast<float2*>(cr + jp * 2) = o;
        }
    }
}

// ---------------------------------------------------------------------------
// Persistent layer-0 LSTM scan. 128 blocks x 512 threads.
// Warp = (jj2 in 2, kh in 8); lanes = (bg in 8, jjg in 4); thread: 4 b, 1 jj,
// 4 gates, k-eighth (kq == kh mod 8). hv LDS dedups 4x across jj in-warp.
// Cross-kh reduction via pad-33 smem buffer aliased on hT.
// ---------------------------------------------------------------------------
__global__ __launch_bounds__(512) void lstm0_scan(const float* __restrict__ Whh)
{
    extern __shared__ float smemf[];
    float4* ws4 = reinterpret_cast<float4*>(smemf);              // [32][256]
    float4* hT4 = reinterpret_cast<float4*>(smemf + 32*256*4);   // [128][33]
    float*  red = smemf + 32*256*4;                              // alias

    const int tid = threadIdx.x;
    const int jbase = blockIdx.x * 8;
    const int w = tid >> 5, kh = w & 7, jj2 = w >> 3;
    const int lane = tid & 31, bg = lane & 7, jjg = lane >> 3;
    const int jj = jj2 * 4 + jjg;

    const int pb = tid & 31, pjj = (tid >> 5) & 7;   // pointwise role (tid<256)
    const int pj = jbase + pjj;

    for (int i = tid; i < 32 * 256; i += 512) {
        int r = i >> 8, kq = i & 255;
        int grow = ((r >> 3) << 10) + jbase + (r & 7);
        ws4[i] = *reinterpret_cast<const float4*>(Whh + (size_t)grow * H + kq * 4);
    }
    __syncthreads();

    for (int t = 0; t < T; t++) {
        float pg0 = 0, pg1 = 0, pg2 = 0, pg3 = 0, cp = 0;
        size_t idx = 0;
        if (tid < 256) {
            const float* xp = g_pre + ((size_t)t * B + pb) * G4 + pj;
            pg0 = xp[0]; pg1 = xp[H]; pg2 = xp[2*H]; pg3 = xp[3*H];
            idx = ((size_t)t * B + pb) * H + pj;
            if (t > 0) cp = g_cbuf[idx - (size_t)(B * H)];
        }

        if (t > 0) {
            ull acc[4][4];
#pragma unroll
            for (int g = 0; g < 4; g++)
#pragma unroll
                for (int i = 0; i < 4; i++) acc[g][i] = 0ULL;

            const float* hprev = g_hbuf + (size_t)(t - 1) * (B * H);
#pragma unroll 1
            for (int c = 0; c < 2; c++) {
                const int kc = c * 512;
                for (int i = tid; i < 4096; i += 512) {
                    int bb = i >> 7, kql = i & 127;
                    hT4[kql * 33 + bb] =
                        *reinterpret_cast<const float4*>(hprev + (size_t)bb * H + kc + kql * 4);
                }
                __syncthreads();
                const int kq0 = c * 128;
#pragma unroll 4
                for (int it = 0; it < 16; it++) {
                    int kq = kh + it * 8;
                    ulonglong2 hv0 = *reinterpret_cast<const ulonglong2*>(&hT4[kq * 33 + bg]);
                    ulonglong2 hv1 = *reinterpret_cast<const ulonglong2*>(&hT4[kq * 33 + bg + 8]);
                    ulonglong2 hv2 = *reinterpret_cast<const ulonglong2*>(&hT4[kq * 33 + bg + 16]);
                    ulonglong2 hv3 = *reinterpret_cast<const ulonglong2*>(&hT4[kq * 33 + bg + 24]);
                    int kqg = kq0 + kq;
#pragma unroll
                    for (int g = 0; g < 4; g++) {
                        ulonglong2 wv = *reinterpret_cast<const ulonglong2*>(
                            &ws4[(g * 8 + jj) * 256 + kqg]);
                        fma2(acc[g][0], wv.x, hv0.x); fma2(acc[g][0], wv.y, hv0.y);
                        fma2(acc[g][1], wv.x, hv1.x); fma2(acc[g][1], wv.y, hv1.y);
                        fma2(acc[g][2], wv.x, hv2.x); fma2(acc[g][2], wv.y, hv2.y);
                        fma2(acc[g][3], wv.x, hv3.x); fma2(acc[g][3], wv.y, hv3.y);
                    }
                }
                __syncthreads();
            }
            // partial sums -> red[(((kh*2+jj2)*4+g)*4+i)*33 + bg*4+jjg]  (b = bg+8i)
#pragma unroll
            for (int g = 0; g < 4; g++)
#pragma unroll
                for (int i = 0; i < 4; i++) {
                    float2 v = unpack2(acc[g][i]);
                    red[((((kh * 2 + jj2) * 4 + g) * 4 + i) * 33) + bg * 4 + jjg] = v.x + v.y;
                }
            __syncthreads();
        }

        if (tid < 256) {
            float sg[4] = {0, 0, 0, 0};
            if (t > 0) {
                const int jj2c = pjj >> 2, jjgc = pjj & 3;
                const int ic = pb >> 3, bgc = pb & 7;
#pragma unroll
                for (int g = 0; g < 4; g++) {
                    float s = 0.0f;
#pragma unroll
                    for (int k8 = 0; k8 < 8; k8++)
                        s += red[((((k8 * 2 + jj2c) * 4 + g) * 4 + ic) * 33) + bgc * 4 + jjgc];
                    sg[g] = s;
                }
            }
            float gi = sg[0] + pg0, gf = sg[1] + pg1, gg = sg[2] + pg2, go = sg[3] + pg3;
            float cc = sigf(gf) * cp + sigf(gi) * tanhf(gg);
            float hh = sigf(go) * tanhf(cc);
            g_hbuf[idx] = hh;
            g_cbuf[idx] = cc;
        }

        if (t < T - 1) grid_bar();
    }
}

// ---------------------------------------------------------------------------
// Persistent CA-LSTM scan (layers 1..3). Same tiling, 5 gates.
// ---------------------------------------------------------------------------
__global__ __launch_bounds__(512) void ca_scan(const float* __restrict__ Wp, int src, int dst)
{
    extern __shared__ float smemf[];
    float4* ws4 = reinterpret_cast<float4*>(smemf);              // [40][256]
    float4* hT4 = reinterpret_cast<float4*>(smemf + 40*256*4);   // [128][33]
    float*  red = smemf + 40*256*4;                              // alias

    const int tid = threadIdx.x;
    const int jbase = blockIdx.x * 8;
    const int w = tid >> 5, kh = w & 7, jj2 = w >> 3;
    const int lane = tid & 31, bg = lane & 7, jjg = lane >> 3;
    const int jj = jj2 * 4 + jjg;

    const int pb = tid & 31, pjj = (tid >> 5) & 7;
    const int pj = jbase + pjj;

    for (int i = tid; i < 40 * 256; i += 512) {
        int r = i >> 8, kq = i & 255;
        int grow = (r >> 3) * H + jbase + (r & 7);
        ws4[i] = *reinterpret_cast<const float4*>(Wp + (size_t)grow * (2 * H) + kq * 4);
    }
    __syncthreads();

    for (int t = 0; t < T; t++) {
        float pg0 = 0, pg1 = 0, pg2 = 0, pg3 = 0, pg4 = 0, cl = 0, cp = 0;
        size_t idx = 0;
        if (tid < 256) {
            const float* pre = g_pre + ((size_t)t * B + pb) * G5 + pj;
            pg0 = pre[0]; pg1 = pre[H]; pg2 = pre[2*H]; pg3 = pre[3*H]; pg4 = pre[4*H];
            idx = ((size_t)t * B + pb) * H + pj;
            cl = g_cbuf[(size_t)src * TBH + idx];
            if (t > 0) cp = g_cbuf[(size_t)dst * TBH + idx - (size_t)(B * H)];
        }

        if (t > 0) {
            ull acc[5][4];
#pragma unroll
            for (int g = 0; g < 5; g++)
#pragma unroll
                for (int i = 0; i < 4; i++) acc[g][i] = 0ULL;

            const float* hprev = g_hbuf + (size_t)dst * TBH + (size_t)(t - 1) * (B * H);
#pragma unroll 1
            for (int c = 0; c < 2; c++) {
                const int kc = c * 512;
                for (int i = tid; i < 4096; i += 512) {
                    int bb = i >> 7, kql = i & 127;
                    hT4[kql * 33 + bb] =
                        *reinterpret_cast<const float4*>(hprev + (size_t)bb * H + kc + kql * 4);
                }
                __syncthreads();
                const int kq0 = c * 128;
#pragma unroll 4
                for (int it = 0; it < 16; it++) {
                    int kq = kh + it * 8;
                    ulonglong2 hv0 = *reinterpret_cast<const ulonglong2*>(&hT4[kq * 33 + bg]);
                    ulonglong2 hv1 = *reinterpret_cast<const ulonglong2*>(&hT4[kq * 33 + bg + 8]);
                    ulonglong2 hv2 = *reinterpret_cast<const ulonglong2*>(&hT4[kq * 33 + bg + 16]);
                    ulonglong2 hv3 = *reinterpret_cast<const ulonglong2*>(&hT4[kq * 33 + bg + 24]);
                    int kqg = kq0 + kq;
#pragma unroll
                    for (int g = 0; g < 5; g++) {
                        ulonglong2 wv = *reinterpret_cast<const ulonglong2*>(
                            &ws4[(g * 8 + jj) * 256 + kqg]);
                        fma2(acc[g][0], wv.x, hv0.x); fma2(acc[g][0], wv.y, hv0.y);
                        fma2(acc[g][1], wv.x, hv1.x); fma2(acc[g][1], wv.y, hv1.y);
                        fma2(acc[g][2], wv.x, hv2.x); fma2(acc[g][2], wv.y, hv2.y);
                        fma2(acc[g][3], wv.x, hv3.x); fma2(acc[g][3], wv.y, hv3.y);
                    }
                }
                __syncthreads();
            }
#pragma unroll
            for (int g = 0; g < 5; g++)
#pragma unroll
                for (int i = 0; i < 4; i++) {
                    float2 v = unpack2(acc[g][i]);
                    red[((((kh * 2 + jj2) * 5 + g) * 4 + i) * 33) + bg * 4 + jjg] = v.x + v.y;
                }
            __syncthreads();
        }

        if (tid < 256) {
            float sg[5] = {0, 0, 0, 0, 0};
            if (t > 0) {
                const int jj2c = pjj >> 2, jjgc = pjj & 3;
                const int ic = pb >> 3, bgc = pb & 7;
#pragma unroll
                for (int g = 0; g < 5; g++) {
                    float s = 0.0f;
#pragma unroll
                    for (int k8 = 0; k8 < 8; k8++)
                        s += red[((((k8 * 2 + jj2c) * 5 + g) * 4 + ic) * 33) + bgc * 4 + jjgc];
                    sg[g] = s;
                }
            }
            float gi  = sg[0] + pg0;
            float gfp = sg[1] + pg1;
            float gfl = sg[2] + pg2;
            float gu  = sg[3] + pg3;
            float go  = sg[4] + pg4;
            float cc = cp * sigf(gfp + 1.0f) + cl * sigf(gfl + 1.0f) + tanhf(gu) * sigf(gi);
            float hh = sigf(go) * tanhf(cc);
            g_hbuf[(size_t)dst * TBH + idx] = hh;
            g_cbuf[(size_t)dst * TBH + idx] = cc;
        }

        if (t < T - 1) grid_bar();
    }
}

// ---------------------------------------------------------------------------
// Final transpose (t,b,j) -> (b,t,j); h then c into d_out.
// ---------------------------------------------------------------------------
__global__ __launch_bounds__(256) void finalize(int fin, float* __restrict__ out)
{
    size_t gid = (size_t)blockIdx.x * 256 + threadIdx.x;
    int j = (int)(gid & (H - 1));
    int bt = (int)(gid >> 10);
    int t = bt & (T - 1);
    int b = bt >> 8;
    size_t srci = ((size_t)t * B + b) * H + j;
    out[gid]       = g_hbuf[(size_t)fin * TBH + srci];
    out[TBH + gid] = g_cbuf[(size_t)fin * TBH + srci];
}

// ---------------------------------------------------------------------------
extern "C" void kernel_launch(void* const* d_in, const int* in_sizes, int n_in,
                              void* d_out, int out_size)
{
    (void)in_sizes; (void)n_in; (void)out_size;
    const float* inputs = (const float*)d_in[0];
    const float* W_ih0  = (const float*)d_in[1];
    const float* W_hh0  = (const float*)d_in[2];
    const float* b_ih0  = (const float*)d_in[3];
    const float* b_hh0  = (const float*)d_in[4];
    const float* W_ca   = (const float*)d_in[5];
    const float* b_ca   = (const float*)d_in[6];
    float* out = (float*)d_out;

    float* pre = nullptr;
    float* hb  = nullptr;
    cudaGetSymbolAddress((void**)&pre, g_pre);
    cudaGetSymbolAddress((void**)&hb,  g_hbuf);

    const int smem0 = 32 * 256 * 16 + 128 * 33 * 16;   // 198656
    const int smemC = 40 * 256 * 16 + 128 * 33 * 16;   // 231424
    cudaFuncSetAttribute(lstm0_scan, cudaFuncAttributeMaxDynamicSharedMemorySize, smem0);
    cudaFuncSetAttribute(ca_scan,    cudaFuncAttributeMaxDynamicSharedMemorySize, smemC);

    gemm_bias<<<dim3(G4 / 128, (B * T) / 128), 256>>>(
        inputs, DI, W_ih0, DI, b_ih0, b_hh0, pre, G4, DI, 1);
    lstm0_scan<<<NBLK, 512, smem0>>>(W_hh0);

    int src = 0;
    for (int l = 0; l < 3; l++) {
        int dst = 1 - src;
        gemm_bias<<<dim3(G5 / 128, (B * T) / 128), 256>>>(
            hb + (size_t)src * TBH, H,
            W_ca + (size_t)l * G5 * (2 * H), 2 * H,
            b_ca + (size_t)l * G5, nullptr,
            pre, G5, H, 0);
        ca_scan<<<NBLK, 512, smemC>>>(W_ca + (size_t)l * G5 * (2 * H) + H, src, dst);
        src = dst;
    }

    finalize<<<(int)(TBH / 256), 256>>>(src, out);
}

// round 8
// speedup vs baseline: 1.9491x; 1.0664x over previous
#include <cuda_runtime.h>
#include <cstdint>
#include <math.h>

#define B 32
#define T 256
#define DI 512
#define H 1024
#define G4 (4*H)
#define G5 (5*H)
#define TBH ((size_t)T*(size_t)B*(size_t)H)
#define NBLK 128
#define WSS 257   // ws row stride in float4 (bank-conflict-free padding)

typedef unsigned long long ull;

// Scratch (allocation-free: __device__ globals)
__device__ float g_pre[(size_t)T*B*G5];     // gate pre-activations
__device__ float g_hbuf[2*TBH];             // ping-pong h sequences, layout (t,b,j)
__device__ float g_cbuf[2*TBH];             // ping-pong c sequences

// Grid barrier state
__device__ unsigned g_cnt;
__device__ volatile unsigned g_gen;

__device__ __forceinline__ float sigf(float x) { return 1.0f / (1.0f + __expf(-x)); }

// Packed f32x2 FMA: d.lo += a.lo*b.lo, d.hi += a.hi*b.hi (1 issue, 2 MACs)
__device__ __forceinline__ void fma2(ull& d, ull a, ull b) {
    asm("fma.rn.f32x2 %0, %1, %2, %0;" : "+l"(d) : "l"(a), "l"(b));
}
__device__ __forceinline__ ull packdup(float x) {
    ull r; asm("mov.b64 %0, {%1, %1};" : "=l"(r) : "f"(x)); return r;
}
__device__ __forceinline__ float2 unpack2(ull v) {
    float2 f; asm("mov.b64 {%0, %1}, %2;" : "=f"(f.x), "=f"(f.y) : "l"(v)); return f;
}

// All-blocks barrier.
__device__ __forceinline__ void grid_bar()
{
    __syncthreads();
    if (threadIdx.x == 0) {
        __threadfence();
        unsigned my = g_gen;
        if (atomicAdd(&g_cnt, 1u) == NBLK - 1) {
            atomicExch(&g_cnt, 0u);
            __threadfence();
            g_gen = my + 1;
        } else {
            while (g_gen == my) { __nanosleep(64); }
            __threadfence();
        }
    }
    __syncthreads();
}

// ---------------------------------------------------------------------------
// GEMM: C[row(m)][n] = sum_k A[m][k] * W[n][k] + b0[n] (+ b1[n])
// 128x128 tile, BK=8, 256 threads, 8x8 per thread, f32x2 packed FMA.
// ---------------------------------------------------------------------------
__global__ __launch_bounds__(256) void gemm_bias(
    const float* __restrict__ A, int lda,
    const float* __restrict__ W, int ldw,
    const float* __restrict__ b0, const float* __restrict__ b1,
    float* __restrict__ C, int ldc, int K, int swapMT)
{
    __shared__ float As[8][128];
    __shared__ float Bs[8][128];

    const int tid = threadIdx.x;
    const int m0 = blockIdx.y * 128;
    const int n0 = blockIdx.x * 128;
    const int tx = tid & 15;
    const int ty = tid >> 4;

    const int ar = tid >> 1;
    const int ac = (tid & 1) * 4;
    const float* Ap = A + (size_t)(m0 + ar) * lda + ac;
    const float* Wp = W + (size_t)(n0 + ar) * ldw + ac;

    ull acc2[8][4];
#pragma unroll
    for (int i = 0; i < 8; i++)
#pragma unroll
        for (int jp = 0; jp < 4; jp++) acc2[i][jp] = 0ULL;

    for (int k0 = 0; k0 < K; k0 += 8) {
        float4 av = *reinterpret_cast<const float4*>(Ap + k0);
        float4 wv = *reinterpret_cast<const float4*>(Wp + k0);
        __syncthreads();
        As[ac + 0][ar] = av.x; As[ac + 1][ar] = av.y;
        As[ac + 2][ar] = av.z; As[ac + 3][ar] = av.w;
        Bs[ac + 0][ar] = wv.x; Bs[ac + 1][ar] = wv.y;
        Bs[ac + 2][ar] = wv.z; Bs[ac + 3][ar] = wv.w;
        __syncthreads();
#pragma unroll
        for (int kk = 0; kk < 8; kk++) {
            const float4* arow = reinterpret_cast<const float4*>(&As[kk][ty * 8]);
            float4 alo = arow[0], ahi = arow[1];
            const ulonglong2* brow = reinterpret_cast<const ulonglong2*>(&Bs[kk][tx * 8]);
            ulonglong2 b01 = brow[0], b23 = brow[1];
            float a[8] = {alo.x, alo.y, alo.z, alo.w, ahi.x, ahi.y, ahi.z, ahi.w};
#pragma unroll
            for (int i = 0; i < 8; i++) {
                ull ad = packdup(a[i]);
                fma2(acc2[i][0], ad, b01.x);
                fma2(acc2[i][1], ad, b01.y);
                fma2(acc2[i][2], ad, b23.x);
                fma2(acc2[i][3], ad, b23.y);
            }
        }
    }

    const int nb = n0 + tx * 8;
#pragma unroll
    for (int i = 0; i < 8; i++) {
        int m = m0 + ty * 8 + i;
        int row = swapMT ? ((m & (T - 1)) * B + (m >> 8)) : m;
        float* cr = C + (size_t)row * ldc + nb;
#pragma unroll
        for (int jp = 0; jp < 4; jp++) {
            float2 v = unpack2(acc2[i][jp]);
            int n = nb + jp * 2;
            float bi0 = b0[n]     + (b1 ? b1[n]     : 0.0f);
            float bi1 = b0[n + 1] + (b1 ? b1[n + 1] : 0.0f);
            float2 o; o.x = v.x + bi0; o.y = v.y + bi1;
            *reinterpret_cast<float2*>(cr + jp * 2) = o;
        }
    }
}

// ---------------------------------------------------------------------------
// Persistent layer-0 LSTM scan. 128 blocks x 512 threads.
// Warp = (jj2 in 2, kh in 8); lanes = (bg in 8, jjg in 4). ws rows padded to
// 257 float4 so the 4 jjg lanes' wv loads start on banks {0,4,8,12}:
// conflict-free (1 wavefront) instead of 4-way serialized.
// ---------------------------------------------------------------------------
__global__ __launch_bounds__(512) void lstm0_scan(const float* __restrict__ Whh)
{
    extern __shared__ float smemf[];
    float4* ws4 = reinterpret_cast<float4*>(smemf);               // [32][WSS]
    float4* hT4 = reinterpret_cast<float4*>(smemf + 32*WSS*4);    // [128][33]
    float*  red = smemf + 32*WSS*4;                               // alias

    const int tid = threadIdx.x;
    const int jbase = blockIdx.x * 8;
    const int w = tid >> 5, kh = w & 7, jj2 = w >> 3;
    const int lane = tid & 31, bg = lane & 7, jjg = lane >> 3;
    const int jj = jj2 * 4 + jjg;

    const int pb = tid & 31, pjj = (tid >> 5) & 7;   // pointwise role (tid<256)
    const int pj = jbase + pjj;

    for (int i = tid; i < 32 * 256; i += 512) {
        int r = i >> 8, kq = i & 255;
        int grow = ((r >> 3) << 10) + jbase + (r & 7);
        ws4[r * WSS + kq] = *reinterpret_cast<const float4*>(Whh + (size_t)grow * H + kq * 4);
    }
    __syncthreads();

    for (int t = 0; t < T; t++) {
        float pg0 = 0, pg1 = 0, pg2 = 0, pg3 = 0, cp = 0;
        size_t idx = 0;
        if (tid < 256) {
            const float* xp = g_pre + ((size_t)t * B + pb) * G4 + pj;
            pg0 = xp[0]; pg1 = xp[H]; pg2 = xp[2*H]; pg3 = xp[3*H];
            idx = ((size_t)t * B + pb) * H + pj;
            if (t > 0) cp = g_cbuf[idx - (size_t)(B * H)];
        }

        if (t > 0) {
            ull acc[4][4];
#pragma unroll
            for (int g = 0; g < 4; g++)
#pragma unroll
                for (int i = 0; i < 4; i++) acc[g][i] = 0ULL;

            const float* hprev = g_hbuf + (size_t)(t - 1) * (B * H);
#pragma unroll 1
            for (int c = 0; c < 2; c++) {
                const int kc = c * 512;
                for (int i = tid; i < 4096; i += 512) {
                    int bb = i >> 7, kql = i & 127;
                    hT4[kql * 33 + bb] =
                        *reinterpret_cast<const float4*>(hprev + (size_t)bb * H + kc + kql * 4);
                }
                __syncthreads();
                const int kq0 = c * 128;
#pragma unroll 4
                for (int it = 0; it < 16; it++) {
                    int kq = kh + it * 8;
                    ulonglong2 hv0 = *reinterpret_cast<const ulonglong2*>(&hT4[kq * 33 + bg]);
                    ulonglong2 hv1 = *reinterpret_cast<const ulonglong2*>(&hT4[kq * 33 + bg + 8]);
                    ulonglong2 hv2 = *reinterpret_cast<const ulonglong2*>(&hT4[kq * 33 + bg + 16]);
                    ulonglong2 hv3 = *reinterpret_cast<const ulonglong2*>(&hT4[kq * 33 + bg + 24]);
                    int kqg = kq0 + kq;
#pragma unroll
                    for (int g = 0; g < 4; g++) {
                        ulonglong2 wv = *reinterpret_cast<const ulonglong2*>(
                            &ws4[(g * 8 + jj) * WSS + kqg]);
                        fma2(acc[g][0], wv.x, hv0.x); fma2(acc[g][0], wv.y, hv0.y);
                        fma2(acc[g][1], wv.x, hv1.x); fma2(acc[g][1], wv.y, hv1.y);
                        fma2(acc[g][2], wv.x, hv2.x); fma2(acc[g][2], wv.y, hv2.y);
                        fma2(acc[g][3], wv.x, hv3.x); fma2(acc[g][3], wv.y, hv3.y);
                    }
                }
                __syncthreads();
            }
#pragma unroll
            for (int g = 0; g < 4; g++)
#pragma unroll
                for (int i = 0; i < 4; i++) {
                    float2 v = unpack2(acc[g][i]);
                    red[((((kh * 2 + jj2) * 4 + g) * 4 + i) * 33) + bg * 4 + jjg] = v.x + v.y;
                }
            __syncthreads();
        }

        if (tid < 256) {
            float sg[4] = {0, 0, 0, 0};
            if (t > 0) {
                const int jj2c = pjj >> 2, jjgc = pjj & 3;
                const int ic = pb >> 3, bgc = pb & 7;
#pragma unroll
                for (int g = 0; g < 4; g++) {
                    float s = 0.0f;
#pragma unroll
                    for (int k8 = 0; k8 < 8; k8++)
                        s += red[((((k8 * 2 + jj2c) * 4 + g) * 4 + ic) * 33) + bgc * 4 + jjgc];
                    sg[g] = s;
                }
            }
            float gi = sg[0] + pg0, gf = sg[1] + pg1, gg = sg[2] + pg2, go = sg[3] + pg3;
            float cc = sigf(gf) * cp + sigf(gi) * tanhf(gg);
            float hh = sigf(go) * tanhf(cc);
            g_hbuf[idx] = hh;
            g_cbuf[idx] = cc;
        }

        if (t < T - 1) grid_bar();
    }
}

// ---------------------------------------------------------------------------
// Persistent CA-LSTM scan (layers 1..3). Same tiling, 5 gates.
// ---------------------------------------------------------------------------
__global__ __launch_bounds__(512) void ca_scan(const float* __restrict__ Wp, int src, int dst)
{
    extern __shared__ float smemf[];
    float4* ws4 = reinterpret_cast<float4*>(smemf);               // [40][WSS]
    float4* hT4 = reinterpret_cast<float4*>(smemf + 40*WSS*4);    // [128][33]
    float*  red = smemf + 40*WSS*4;                               // alias

    const int tid = threadIdx.x;
    const int jbase = blockIdx.x * 8;
    const int w = tid >> 5, kh = w & 7, jj2 = w >> 3;
    const int lane = tid & 31, bg = lane & 7, jjg = lane >> 3;
    const int jj = jj2 * 4 + jjg;

    const int pb = tid & 31, pjj = (tid >> 5) & 7;
    const int pj = jbase + pjj;

    for (int i = tid; i < 40 * 256; i += 512) {
        int r = i >> 8, kq = i & 255;
        int grow = (r >> 3) * H + jbase + (r & 7);
        ws4[r * WSS + kq] = *reinterpret_cast<const float4*>(Wp + (size_t)grow * (2 * H) + kq * 4);
    }
    __syncthreads();

    for (int t = 0; t < T; t++) {
        float pg0 = 0, pg1 = 0, pg2 = 0, pg3 = 0, pg4 = 0, cl = 0, cp = 0;
        size_t idx = 0;
        if (tid < 256) {
            const float* pre = g_pre + ((size_t)t * B + pb) * G5 + pj;
            pg0 = pre[0]; pg1 = pre[H]; pg2 = pre[2*H]; pg3 = pre[3*H]; pg4 = pre[4*H];
            idx = ((size_t)t * B + pb) * H + pj;
            cl = g_cbuf[(size_t)src * TBH + idx];
            if (t > 0) cp = g_cbuf[(size_t)dst * TBH + idx - (size_t)(B * H)];
        }

        if (t > 0) {
            ull acc[5][4];
#pragma unroll
            for (int g = 0; g < 5; g++)
#pragma unroll
                for (int i = 0; i < 4; i++) acc[g][i] = 0ULL;

            const float* hprev = g_hbuf + (size_t)dst * TBH + (size_t)(t - 1) * (B * H);
#pragma unroll 1
            for (int c = 0; c < 2; c++) {
                const int kc = c * 512;
                for (int i = tid; i < 4096; i += 512) {
                    int bb = i >> 7, kql = i & 127;
                    hT4[kql * 33 + bb] =
                        *reinterpret_cast<const float4*>(hprev + (size_t)bb * H + kc + kql * 4);
                }
                __syncthreads();
                const int kq0 = c * 128;
#pragma unroll 4
                for (int it = 0; it < 16; it++) {
                    int kq = kh + it * 8;
                    ulonglong2 hv0 = *reinterpret_cast<const ulonglong2*>(&hT4[kq * 33 + bg]);
                    ulonglong2 hv1 = *reinterpret_cast<const ulonglong2*>(&hT4[kq * 33 + bg + 8]);
                    ulonglong2 hv2 = *reinterpret_cast<const ulonglong2*>(&hT4[kq * 33 + bg + 16]);
                    ulonglong2 hv3 = *reinterpret_cast<const ulonglong2*>(&hT4[kq * 33 + bg + 24]);
                    int kqg = kq0 + kq;
#pragma unroll
                    for (int g = 0; g < 5; g++) {
                        ulonglong2 wv = *reinterpret_cast<const ulonglong2*>(
                            &ws4[(g * 8 + jj) * WSS + kqg]);
                        fma2(acc[g][0], wv.x, hv0.x); fma2(acc[g][0], wv.y, hv0.y);
                        fma2(acc[g][1], wv.x, hv1.x); fma2(acc[g][1], wv.y, hv1.y);
                        fma2(acc[g][2], wv.x, hv2.x); fma2(acc[g][2], wv.y, hv2.y);
                        fma2(acc[g][3], wv.x, hv3.x); fma2(acc[g][3], wv.y, hv3.y);
                    }
                }
                __syncthreads();
            }
#pragma unroll
            for (int g = 0; g < 5; g++)
#pragma unroll
                for (int i = 0; i < 4; i++) {
                    float2 v = unpack2(acc[g][i]);
                    red[((((kh * 2 + jj2) * 5 + g) * 4 + i) * 33) + bg * 4 + jjg] = v.x + v.y;
                }
            __syncthreads();
        }

        if (tid < 256) {
            float sg[5] = {0, 0, 0, 0, 0};
            if (t > 0) {
                const int jj2c = pjj >> 2, jjgc = pjj & 3;
                const int ic = pb >> 3, bgc = pb & 7;
#pragma unroll
                for (int g = 0; g < 5; g++) {
                    float s = 0.0f;
#pragma unroll
                    for (int k8 = 0; k8 < 8; k8++)
                        s += red[((((k8 * 2 + jj2c) * 5 + g) * 4 + ic) * 33) + bgc * 4 + jjgc];
                    sg[g] = s;
                }
            }
            float gi  = sg[0] + pg0;
            float gfp = sg[1] + pg1;
            float gfl = sg[2] + pg2;
            float gu  = sg[3] + pg3;
            float go  = sg[4] + pg4;
            float cc = cp * sigf(gfp + 1.0f) + cl * sigf(gfl + 1.0f) + tanhf(gu) * sigf(gi);
            float hh = sigf(go) * tanhf(cc);
            g_hbuf[(size_t)dst * TBH + idx] = hh;
            g_cbuf[(size_t)dst * TBH + idx] = cc;
        }

        if (t < T - 1) grid_bar();
    }
}

// ---------------------------------------------------------------------------
// Final transpose (t,b,j) -> (b,t,j); h then c into d_out.
// ---------------------------------------------------------------------------
__global__ __launch_bounds__(256) void finalize(int fin, float* __restrict__ out)
{
    size_t gid = (size_t)blockIdx.x * 256 + threadIdx.x;
    int j = (int)(gid & (H - 1));
    int bt = (int)(gid >> 10);
    int t = bt & (T - 1);
    int b = bt >> 8;
    size_t srci = ((size_t)t * B + b) * H + j;
    out[gid]       = g_hbuf[(size_t)fin * TBH + srci];
    out[TBH + gid] = g_cbuf[(size_t)fin * TBH + srci];
}

// ---------------------------------------------------------------------------
extern "C" void kernel_launch(void* const* d_in, const int* in_sizes, int n_in,
                              void* d_out, int out_size)
{
    (void)in_sizes; (void)n_in; (void)out_size;
    const float* inputs = (const float*)d_in[0];
    const float* W_ih0  = (const float*)d_in[1];
    const float* W_hh0  = (const float*)d_in[2];
    const float* b_ih0  = (const float*)d_in[3];
    const float* b_hh0  = (const float*)d_in[4];
    const float* W_ca   = (const float*)d_in[5];
    const float* b_ca   = (const float*)d_in[6];
    float* out = (float*)d_out;

    float* pre = nullptr;
    float* hb  = nullptr;
    cudaGetSymbolAddress((void**)&pre, g_pre);
    cudaGetSymbolAddress((void**)&hb,  g_hbuf);

    const int smem0 = 32 * WSS * 16 + 128 * 33 * 16;   // 199168
    const int smemC = 40 * WSS * 16 + 128 * 33 * 16;   // 232064
    cudaFuncSetAttribute(lstm0_scan, cudaFuncAttributeMaxDynamicSharedMemorySize, smem0);
    cudaFuncSetAttribute(ca_scan,    cudaFuncAttributeMaxDynamicSharedMemorySize, smemC);

    gemm_bias<<<dim3(G4 / 128, (B * T) / 128), 256>>>(
        inputs, DI, W_ih0, DI, b_ih0, b_hh0, pre, G4, DI, 1);
    lstm0_scan<<<NBLK, 512, smem0>>>(W_hh0);

    int src = 0;
    for (int l = 0; l < 3; l++) {
        int dst = 1 - src;
        gemm_bias<<<dim3(G5 / 128, (B * T) / 128), 256>>>(
            hb + (size_t)src * TBH, H,
            W_ca + (size_t)l * G5 * (2 * H), 2 * H,
            b_ca + (size_t)l * G5, nullptr,
            pre, G5, H, 0);
        ca_scan<<<NBLK, 512, smemC>>>(W_ca + (size_t)l * G5 * (2 * H) + H, src, dst);
        src = dst;
    }

    finalize<<<(int)(TBH / 256), 256>>>(src, out);
}

// round 11
// speedup vs baseline: 2.0483x; 1.0509x over previous
#include <cuda_runtime.h>
#include <cstdint>
#include <math.h>

#define B 32
#define T 256
#define DI 512
#define H 1024
#define G4 (4*H)
#define G5 (5*H)
#define TBH ((size_t)T*(size_t)B*(size_t)H)
#define NBLK 128
#define WSS 257   // ws row stride in float4 (bank-conflict-free padding)

typedef unsigned long long ull;

// Scratch (allocation-free: __device__ globals)
__device__ float g_pre[(size_t)T*B*G5];     // gate pre-activations
__device__ float g_hbuf[2*TBH];             // ping-pong h sequences, layout (t,b,j)
__device__ float g_cbuf[2*TBH];             // ping-pong c sequences

// Grid barrier state
__device__ unsigned g_cnt;
__device__ volatile unsigned g_gen;

__device__ __forceinline__ float sigf(float x) { return 1.0f / (1.0f + __expf(-x)); }

__device__ __forceinline__ void fma2(ull& d, ull a, ull b) {
    asm("fma.rn.f32x2 %0, %1, %2, %0;" : "+l"(d) : "l"(a), "l"(b));
}
__device__ __forceinline__ ull packdup(float x) {
    ull r; asm("mov.b64 %0, {%1, %1};" : "=l"(r) : "f"(x)); return r;
}
__device__ __forceinline__ float2 unpack2(ull v) {
    float2 f; asm("mov.b64 {%0, %1}, %2;" : "=f"(f.x), "=f"(f.y) : "l"(v)); return f;
}
__device__ __forceinline__ unsigned smem_u32(const void* p) {
    return (unsigned)__cvta_generic_to_shared(p);
}
__device__ __forceinline__ void cpasync16(unsigned dst, const void* src) {
    asm volatile("cp.async.ca.shared.global [%0], [%1], 16;" :: "r"(dst), "l"(src));
}
__device__ __forceinline__ void cpasync_commit_wait() {
    asm volatile("cp.async.commit_group;");
    asm volatile("cp.async.wait_group 0;");
}

// All-blocks barrier.
__device__ __forceinline__ void grid_bar()
{
    __syncthreads();
    if (threadIdx.x == 0) {
        __threadfence();
        unsigned my = g_gen;
        if (atomicAdd(&g_cnt, 1u) == NBLK - 1) {
            atomicExch(&g_cnt, 0u);
            __threadfence();
            g_gen = my + 1;
        } else {
            while (g_gen == my) { __nanosleep(32); }
            __threadfence();
        }
    }
    __syncthreads();
}

// ---------------------------------------------------------------------------
// GEMM: C[row(m)][n] = sum_k A[m][k] * W[n][k] + b0[n] (+ b1[n])
// ---------------------------------------------------------------------------
__global__ __launch_bounds__(256) void gemm_bias(
    const float* __restrict__ A, int lda,
    const float* __restrict__ W, int ldw,
    const float* __restrict__ b0, const float* __restrict__ b1,
    float* __restrict__ C, int ldc, int K, int swapMT)
{
    __shared__ float As[8][128];
    __shared__ float Bs[8][128];

    const int tid = threadIdx.x;
    const int m0 = blockIdx.y * 128;
    const int n0 = blockIdx.x * 128;
    const int tx = tid & 15;
    const int ty = tid >> 4;

    const int ar = tid >> 1;
    const int ac = (tid & 1) * 4;
    const float* Ap = A + (size_t)(m0 + ar) * lda + ac;
    const float* Wp = W + (size_t)(n0 + ar) * ldw + ac;

    ull acc2[8][4];
#pragma unroll
    for (int i = 0; i < 8; i++)
#pragma unroll
        for (int jp = 0; jp < 4; jp++) acc2[i][jp] = 0ULL;

    for (int k0 = 0; k0 < K; k0 += 8) {
        float4 av = *reinterpret_cast<const float4*>(Ap + k0);
        float4 wv = *reinterpret_cast<const float4*>(Wp + k0);
        __syncthreads();
        As[ac + 0][ar] = av.x; As[ac + 1][ar] = av.y;
        As[ac + 2][ar] = av.z; As[ac + 3][ar] = av.w;
        Bs[ac + 0][ar] = wv.x; Bs[ac + 1][ar] = wv.y;
        Bs[ac + 2][ar] = wv.z; Bs[ac + 3][ar] = wv.w;
        __syncthreads();
#pragma unroll
        for (int kk = 0; kk < 8; kk++) {
            const float4* arow = reinterpret_cast<const float4*>(&As[kk][ty * 8]);
            float4 alo = arow[0], ahi = arow[1];
            const ulonglong2* brow = reinterpret_cast<const ulonglong2*>(&Bs[kk][tx * 8]);
            ulonglong2 b01 = brow[0], b23 = brow[1];
            float a[8] = {alo.x, alo.y, alo.z, alo.w, ahi.x, ahi.y, ahi.z, ahi.w};
#pragma unroll
            for (int i = 0; i < 8; i++) {
                ull ad = packdup(a[i]);
                fma2(acc2[i][0], ad, b01.x);
                fma2(acc2[i][1], ad, b01.y);
                fma2(acc2[i][2], ad, b23.x);
                fma2(acc2[i][3], ad, b23.y);
            }
        }
    }

    const int nb = n0 + tx * 8;
#pragma unroll
    for (int i = 0; i < 8; i++) {
        int m = m0 + ty * 8 + i;
        int row = swapMT ? ((m & (T - 1)) * B + (m >> 8)) : m;
        float* cr = C + (size_t)row * ldc + nb;
#pragma unroll
        for (int jp = 0; jp < 4; jp++) {
            float2 v = unpack2(acc2[i][jp]);
            int n = nb + jp * 2;
            float bi0 = b0[n]     + (b1 ? b1[n]     : 0.0f);
            float bi1 = b0[n + 1] + (b1 ? b1[n + 1] : 0.0f);
            float2 o; o.x = v.x + bi0; o.y = v.y + bi1;
            *reinterpret_cast<float2*>(cr + jp * 2) = o;
        }
    }
}

// ---------------------------------------------------------------------------
// Persistent layer-0 LSTM scan. 128 blocks x 512 threads.
// Compute warps: (jj2 in 2, kh in 8); lanes (bg in 8, jjg in 4).
// Pointwise (tid<256): j8 = tid&7 (fast) x b = tid>>3 -> coalesced gmem.
// c carried in register. h staged with cp.async.
// ---------------------------------------------------------------------------
__global__ __launch_bounds__(512) void lstm0_scan(const float* __restrict__ Whh)
{
    extern __shared__ float smemf[];
    float4* ws4 = reinterpret_cast<float4*>(smemf);               // [32][WSS]
    float4* hT4 = reinterpret_cast<float4*>(smemf + 32*WSS*4);    // [128][33]
    float*  red = smemf + 32*WSS*4;                               // alias

    const int tid = threadIdx.x;
    const int jbase = blockIdx.x * 8;
    const int w = tid >> 5, kh = w & 7, jj2 = w >> 3;
    const int lane = tid & 31, bg = lane & 7, jjg = lane >> 3;
    const int jj = jj2 * 4 + jjg;

    const int pj8 = tid & 7, pbb = tid >> 3;   // pointwise role (tid<256)
    const int pj = jbase + pj8;
    float creg = 0.0f;
    const unsigned hbase = smem_u32(hT4);

    for (int i = tid; i < 32 * 256; i += 512) {
        int r = i >> 8, kq = i & 255;
        int grow = ((r >> 3) << 10) + jbase + (r & 7);
        ws4[r * WSS + kq] = *reinterpret_cast<const float4*>(Whh + (size_t)grow * H + kq * 4);
    }
    __syncthreads();

    for (int t = 0; t < T; t++) {
        float pg0 = 0, pg1 = 0, pg2 = 0, pg3 = 0;
        size_t idx = 0;
        if (tid < 256) {
            const float* xp = g_pre + ((size_t)t * B + pbb) * G4 + pj;
            pg0 = xp[0]; pg1 = xp[H]; pg2 = xp[2*H]; pg3 = xp[3*H];
            idx = ((size_t)t * B + pbb) * H + pj;
        }

        if (t > 0) {
            ull acc[4][4];
#pragma unroll
            for (int g = 0; g < 4; g++)
#pragma unroll
                for (int i = 0; i < 4; i++) acc[g][i] = 0ULL;

            const float* hprev = g_hbuf + (size_t)(t - 1) * (B * H);
#pragma unroll 1
            for (int c = 0; c < 2; c++) {
                const int kc = c * 512;
#pragma unroll
                for (int it2 = 0; it2 < 8; it2++) {
                    int i = tid + it2 * 512;
                    int bb = i >> 7, kql = i & 127;
                    cpasync16(hbase + (unsigned)(kql * 33 + bb) * 16,
                              hprev + (size_t)bb * H + kc + kql * 4);
                }
                cpasync_commit_wait();
                __syncthreads();
                const int kq0 = c * 128;
#pragma unroll 4
                for (int it = 0; it < 16; it++) {
                    int kq = kh + it * 8;
                    ulonglong2 hv0 = *reinterpret_cast<const ulonglong2*>(&hT4[kq * 33 + bg]);
                    ulonglong2 hv1 = *reinterpret_cast<const ulonglong2*>(&hT4[kq * 33 + bg + 8]);
                    ulonglong2 hv2 = *reinterpret_cast<const ulonglong2*>(&hT4[kq * 33 + bg + 16]);
                    ulonglong2 hv3 = *reinterpret_cast<const ulonglong2*>(&hT4[kq * 33 + bg + 24]);
                    int kqg = kq0 + kq;
#pragma unroll
                    for (int g = 0; g < 4; g++) {
                        ulonglong2 wv = *reinterpret_cast<const ulonglong2*>(
                            &ws4[(g * 8 + jj) * WSS + kqg]);
                        fma2(acc[g][0], wv.x, hv0.x); fma2(acc[g][0], wv.y, hv0.y);
                        fma2(acc[g][1], wv.x, hv1.x); fma2(acc[g][1], wv.y, hv1.y);
                        fma2(acc[g][2], wv.x, hv2.x); fma2(acc[g][2], wv.y, hv2.y);
                        fma2(acc[g][3], wv.x, hv3.x); fma2(acc[g][3], wv.y, hv3.y);
                    }
                }
                __syncthreads();
            }
#pragma unroll
            for (int g = 0; g < 4; g++)
#pragma unroll
                for (int i = 0; i < 4; i++) {
                    float2 v = unpack2(acc[g][i]);
                    red[((((kh * 2 + jj2) * 4 + g) * 4 + i) * 33) + bg * 4 + jjg] = v.x + v.y;
                }
            __syncthreads();
        }

        if (tid < 256) {
            float sg[4] = {0, 0, 0, 0};
            if (t > 0) {
                const int jj2c = pj8 >> 2, jjgc = pj8 & 3;
                const int ic = pbb >> 3, bgc = pbb & 7;
#pragma unroll
                for (int g = 0; g < 4; g++) {
                    float s = 0.0f;
#pragma unroll
                    for (int k8 = 0; k8 < 8; k8++)
                        s += red[((((k8 * 2 + jj2c) * 4 + g) * 4 + ic) * 33) + bgc * 4 + jjgc];
                    sg[g] = s;
                }
            }
            float gi = sg[0] + pg0, gf = sg[1] + pg1, gg = sg[2] + pg2, go = sg[3] + pg3;
            float cc = sigf(gf) * creg + sigf(gi) * tanhf(gg);
            float hh = sigf(go) * tanhf(cc);
            creg = cc;
            g_hbuf[idx] = hh;
            g_cbuf[idx] = cc;
        }

        if (t < T - 1) grid_bar();
    }
}

// ---------------------------------------------------------------------------
// Persistent CA-LSTM scan (layers 1..3). Same tiling, 5 gates.
// ---------------------------------------------------------------------------
__global__ __launch_bounds__(512) void ca_scan(const float* __restrict__ Wp, int src, int dst)
{
    extern __shared__ float smemf[];
    float4* ws4 = reinterpret_cast<float4*>(smemf);               // [40][WSS]
    float4* hT4 = reinterpret_cast<float4*>(smemf + 40*WSS*4);    // [128][33]
    float*  red = smemf + 40*WSS*4;                               // alias

    const int tid = threadIdx.x;
    const int jbase = blockIdx.x * 8;
    const int w = tid >> 5, kh = w & 7, jj2 = w >> 3;
    const int lane = tid & 31, bg = lane & 7, jjg = lane >> 3;
    const int jj = jj2 * 4 + jjg;

    const int pj8 = tid & 7, pbb = tid >> 3;   // pointwise role (tid<256)
    const int pj = jbase + pj8;
    float creg = 0.0f;
    const unsigned hbase = smem_u32(hT4);

    for (int i = tid; i < 40 * 256; i += 512) {
        int r = i >> 8, kq = i & 255;
        int grow = (r >> 3) * H + jbase + (r & 7);
        ws4[r * WSS + kq] = *reinterpret_cast<const float4*>(Wp + (size_t)grow * (2 * H) + kq * 4);
    }
    __syncthreads();

    for (int t = 0; t < T; t++) {
        float pg0 = 0, pg1 = 0, pg2 = 0, pg3 = 0, pg4 = 0, cl = 0;
        size_t idx = 0;
        if (tid < 256) {
            const float* pre = g_pre + ((size_t)t * B + pbb) * G5 + pj;
            pg0 = pre[0]; pg1 = pre[H]; pg2 = pre[2*H]; pg3 = pre[3*H]; pg4 = pre[4*H];
            idx = ((size_t)t * B + pbb) * H + pj;
            cl = g_cbuf[(size_t)src * TBH + idx];
        }

        if (t > 0) {
            ull acc[5][4];
#pragma unroll
            for (int g = 0; g < 5; g++)
#pragma unroll
                for (int i = 0; i < 4; i++) acc[g][i] = 0ULL;

            const float* hprev = g_hbuf + (size_t)dst * TBH + (size_t)(t - 1) * (B * H);
#pragma unroll 1
            for (int c = 0; c < 2; c++) {
                const int kc = c * 512;
#pragma unroll
                for (int it2 = 0; it2 < 8; it2++) {
                    int i = tid + it2 * 512;
                    int bb = i >> 7, kql = i & 127;
                    cpasync16(hbase + (unsigned)(kql * 33 + bb) * 16,
                              hprev + (size_t)bb * H + kc + kql * 4);
                }
                cpasync_commit_wait();
                __syncthreads();
                const int kq0 = c * 128;
#pragma unroll 4
                for (int it = 0; it < 16; it++) {
                    int kq = kh + it * 8;
                    ulonglong2 hv0 = *reinterpret_cast<const ulonglong2*>(&hT4[kq * 33 + bg]);
                    ulonglong2 hv1 = *reinterpret_cast<const ulonglong2*>(&hT4[kq * 33 + bg + 8]);
                    ulonglong2 hv2 = *reinterpret_cast<const ulonglong2*>(&hT4[kq * 33 + bg + 16]);
                    ulonglong2 hv3 = *reinterpret_cast<const ulonglong2*>(&hT4[kq * 33 + bg + 24]);
                    int kqg = kq0 + kq;
#pragma unroll
                    for (int g = 0; g < 5; g++) {
                        ulonglong2 wv = *reinterpret_cast<const ulonglong2*>(
                            &ws4[(g * 8 + jj) * WSS + kqg]);
                        fma2(acc[g][0], wv.x, hv0.x); fma2(acc[g][0], wv.y, hv0.y);
                        fma2(acc[g][1], wv.x, hv1.x); fma2(acc[g][1], wv.y, hv1.y);
                        fma2(acc[g][2], wv.x, hv2.x); fma2(acc[g][2], wv.y, hv2.y);
                        fma2(acc[g][3], wv.x, hv3.x); fma2(acc[g][3], wv.y, hv3.y);
                    }
                }
                __syncthreads();
            }
#pragma unroll
            for (int g = 0; g < 5; g++)
#pragma unroll
                for (int i = 0; i < 4; i++) {
                    float2 v = unpack2(acc[g][i]);
                    red[((((kh * 2 + jj2) * 5 + g) * 4 + i) * 33) + bg * 4 + jjg] = v.x + v.y;
                }
            __syncthreads();
        }

        if (tid < 256) {
            float sg[5] = {0, 0, 0, 0, 0};
            if (t > 0) {
                const int jj2c = pj8 >> 2, jjgc = pj8 & 3;
                const int ic = pbb >> 3, bgc = pbb & 7;
#pragma unroll
                for (int g = 0; g < 5; g++) {
                    float s = 0.0f;
#pragma unroll
                    for (int k8 = 0; k8 < 8; k8++)
                        s += red[((((k8 * 2 + jj2c) * 5 + g) * 4 + ic) * 33) + bgc * 4 + jjgc];
                    sg[g] = s;
                }
            }
            float gi  = sg[0] + pg0;
            float gfp = sg[1] + pg1;
            float gfl = sg[2] + pg2;
            float gu  = sg[3] + pg3;
            float go  = sg[4] + pg4;
            float cc = creg * sigf(gfp + 1.0f) + cl * sigf(gfl + 1.0f) + tanhf(gu) * sigf(gi);
            float hh = sigf(go) * tanhf(cc);
            creg = cc;
            g_hbuf[(size_t)dst * TBH + idx] = hh;
            g_cbuf[(size_t)dst * TBH + idx] = cc;
        }

        if (t < T - 1) grid_bar();
    }
}

// ---------------------------------------------------------------------------
// Final transpose (t,b,j) -> (b,t,j); h then c into d_out.
// ---------------------------------------------------------------------------
__global__ __launch_bounds__(256) void finalize(int fin, float* __restrict__ out)
{
    size_t gid = (size_t)blockIdx.x * 256 + threadIdx.x;
    int j = (int)(gid & (H - 1));
    int bt = (int)(gid >> 10);
    int t = bt & (T - 1);
    int b = bt >> 8;
    size_t srci = ((size_t)t * B + b) * H + j;
    out[gid]       = g_hbuf[(size_t)fin * TBH + srci];
    out[TBH + gid] = g_cbuf[(size_t)fin * TBH + srci];
}

// ---------------------------------------------------------------------------
extern "C" void kernel_launch(void* const* d_in, const int* in_sizes, int n_in,
                              void* d_out, int out_size)
{
    (void)in_sizes; (void)n_in; (void)out_size;
    const float* inputs = (const float*)d_in[0];
    const float* W_ih0  = (const float*)d_in[1];
    const float* W_hh0  = (const float*)d_in[2];
    const float* b_ih0  = (const float*)d_in[3];
    const float* b_hh0  = (const float*)d_in[4];
    const float* W_ca   = (const float*)d_in[5];
    const float* b_ca   = (const float*)d_in[6];
    float* out = (float*)d_out;

    float* pre = nullptr;
    float* hb  = nullptr;
    cudaGetSymbolAddress((void**)&pre, g_pre);
    cudaGetSymbolAddress((void**)&hb,  g_hbuf);

    const int smem0 = 32 * WSS * 16 + 128 * 33 * 16;   // 199168
    const int smemC = 40 * WSS * 16 + 128 * 33 * 16;   // 232064
    cudaFuncSetAttribute(lstm0_scan, cudaFuncAttributeMaxDynamicSharedMemorySize, smem0);
    cudaFuncSetAttribute(ca_scan,    cudaFuncAttributeMaxDynamicSharedMemorySize, smemC);

    gemm_bias<<<dim3(G4 / 128, (B * T) / 128), 256>>>(
        inputs, DI, W_ih0, DI, b_ih0, b_hh0, pre, G4, DI, 1);
    lstm0_scan<<<NBLK, 512, smem0>>>(W_hh0);

    int src = 0;
    for (int l = 0; l < 3; l++) {
        int dst = 1 - src;
        gemm_bias<<<dim3(G5 / 128, (B * T) / 128), 256>>>(
            hb + (size_t)src * TBH, H,
            W_ca + (size_t)l * G5 * (2 * H), 2 * H,
            b_ca + (size_t)l * G5, nullptr,
            pre, G5, H, 0);
        ca_scan<<<NBLK, 512, smemC>>>(W_ca + (size_t)l * G5 * (2 * H) + H, src, dst);
        src = dst;
    }

    finalize<<<(int)(TBH / 256), 256>>>(src, out);
}